// round 2
// baseline (speedup 1.0000x reference)
#include <cuda_runtime.h>

#define WIRE_DIM   32
#define NUM_WIRES  64
#define ROW_ELEMS  (NUM_WIRES * WIRE_DIM)   // 2048 floats per batch row
#define BPB        4                        // batch rows per block (1 warp each)
#define NTHREADS   (BPB * 32)
#define XS         33                       // padded smem stride (bank-conflict-free)

// ---- packed f32x2 helpers (Blackwell FFMA2 via PTX; ptxas will not auto-fuse) ----
__device__ __forceinline__ unsigned long long pack2(float v) {
    unsigned long long r;
    asm("mov.b64 %0, {%1, %1};" : "=l"(r) : "f"(v));
    return r;
}
__device__ __forceinline__ void ffma2(unsigned long long &d,
                                      unsigned long long a,
                                      unsigned long long b) {
    asm("fma.rn.f32x2 %0, %1, %2, %0;" : "+l"(d) : "l"(a), "l"(b));
}
__device__ __forceinline__ float2 unpack2(unsigned long long v) {
    float2 f;
    asm("mov.b64 {%0, %1}, %2;" : "=f"(f.x), "=f"(f.y) : "l"(v));
    return f;
}

__global__ __launch_bounds__(NTHREADS)
void trainer_kernel(const float* __restrict__ outputs,
                    const int* __restrict__ tests_i32,   // raw test buffer, width detected
                    const float* __restrict__ W1,
                    const float* __restrict__ b1,
                    const float* __restrict__ W2,
                    const float* __restrict__ b2,
                    float* __restrict__ out,
                    int B)
{
    __shared__ __align__(16) float sW1[64 * 10];            // 2560 B
    __shared__ __align__(16) float sb1[12];
    __shared__ __align__(16) float sW2[12];
    __shared__ __align__(16) float spc[BPB][12];            // person contribution
    __shared__ __align__(16) float sx[BPB][NUM_WIRES * XS]; // 4 * 64*33*4 = 33792 B

    const int tid  = threadIdx.x;
    const int warp = tid >> 5;
    const int lane = tid & 31;
    const int b    = blockIdx.x * BPB + warp;
    const bool valid = (b < B);

    // --- stage weights into smem (block-cooperative) ---
    for (int i = tid; i < 640; i += NTHREADS) sW1[i] = W1[i];
    if (tid < 10) { sb1[tid] = b1[tid]; sW2[tid] = W2[tid]; }

    // --- detect tests dtype: int64 pairs have zero high-words at odd int32 slots.
    // Reading the first 64 ints is in-bounds for both layouts (>=64KB each).
    int hiword_or = 0;
    {
        int v = tests_i32[2 * lane + 1];          // lanes cover odd idx 1..63
        #pragma unroll
        for (int o = 16; o > 0; o >>= 1)
            v |= __shfl_xor_sync(0xffffffffu, v, o);
        hiword_or = v;
    }
    const bool is_i64 = (hiword_or == 0);

    // --- coalesced copy of this warp's batch row: gmem float4 -> padded smem ---
    if (valid) {
        const float4* src = (const float4*)(outputs + (size_t)b * ROW_ELEMS);
        #pragma unroll
        for (int t = 0; t < 16; t++) {
            int   f  = t * 32 + lane;        // float4 index 0..511
            float4 v = src[f];
            int   w  = f >> 3;               // wire index (8 float4 per wire)
            int   d0 = (f & 7) << 2;         // dim offset within wire
            float* dst = &sx[warp][w * XS + d0];
            // scalar STS: banks (w + 4j + k) % 32 -> conflict-free across the warp
            dst[0] = v.x; dst[1] = v.y; dst[2] = v.z; dst[3] = v.w;
        }
    }
    __syncthreads();   // covers sW1/sb1/sW2 and sx

    int person = 0, loc = 0;
    if (valid) {
        if (is_i64) {   // little-endian int64 pairs: low words at 4b, 4b+2
            person = tests_i32[4 * b];
            loc    = tests_i32[4 * b + 2];
        } else {        // plain int32 pairs
            person = tests_i32[2 * b];
            loc    = tests_i32[2 * b + 1];
        }
    }

    // --- person contribution pc[h] = b1[h] + sum_d pv[d] * W1[d][h] (lanes 0..9) ---
    if (valid && lane < 10) {
        const float* prow = &sx[warp][person * XS];
        float pc = sb1[lane];
        #pragma unroll
        for (int d = 0; d < 32; d++) pc += prow[d] * sW1[d * 10 + lane];
        spc[warp][lane] = pc;
    }
    __syncwarp();

    if (valid) {
        // --- main MLP: lane handles wires (2*lane) and (2*lane+1), packed f32x2 over h ---
        const float* xa = &sx[warp][(2 * lane) * XS];
        const float* xb = xa + XS;

        unsigned long long accA[5], accB[5];
        const unsigned long long* pcp = (const unsigned long long*)&spc[warp][0];
        #pragma unroll
        for (int h = 0; h < 5; h++) { accA[h] = pcp[h]; accB[h] = pcp[h]; }

        #pragma unroll
        for (int d = 0; d < 32; d++) {
            unsigned long long av = pack2(xa[d]);
            unsigned long long bv = pack2(xb[d]);
            const float* wrow = &sW1[(32 + d) * 10];   // (32+d)*10 floats: 8B-aligned
            #pragma unroll
            for (int h = 0; h < 5; h++) {
                unsigned long long wv = *(const unsigned long long*)(wrow + 2 * h);
                ffma2(accA[h], av, wv);
                ffma2(accB[h], bv, wv);
            }
        }

        // --- relu + output layer -> two logits per lane ---
        float b2v = __ldg(b2);
        float la = b2v, lb = b2v;
        #pragma unroll
        for (int h = 0; h < 5; h++) {
            float2 fa = unpack2(accA[h]);
            float2 fb = unpack2(accB[h]);
            float w0 = sW2[2 * h], w1 = sW2[2 * h + 1];
            la += fmaxf(fa.x, 0.f) * w0 + fmaxf(fa.y, 0.f) * w1;
            lb += fmaxf(fb.x, 0.f) * w0 + fmaxf(fb.y, 0.f) * w1;
        }

        // --- warp log-softmax over 64 logits, pick location ---
        float m = fmaxf(la, lb);
        #pragma unroll
        for (int o = 16; o > 0; o >>= 1)
            m = fmaxf(m, __shfl_xor_sync(0xffffffffu, m, o));
        float s = __expf(la - m) + __expf(lb - m);
        #pragma unroll
        for (int o = 16; o > 0; o >>= 1)
            s += __shfl_xor_sync(0xffffffffu, s, o);

        float chosen = (loc & 1) ? lb : la;        // loc is warp-uniform
        chosen = __shfl_sync(0xffffffffu, chosen, loc >> 1);

        if (lane == 0) out[b] = -(chosen - m - __logf(s));
    }
}

extern "C" void kernel_launch(void* const* d_in, const int* in_sizes, int n_in,
                              void* d_out, int out_size)
{
    const float* outputs = (const float*)d_in[0];
    const int*   tests   = (const int*)d_in[1];
    const float* W1      = (const float*)d_in[2];
    const float* b1      = (const float*)d_in[3];
    const float* W2      = (const float*)d_in[4];
    const float* b2      = (const float*)d_in[5];
    float* out = (float*)d_out;
    int B = out_size;                 // one loss per batch element

    int blocks = (B + BPB - 1) / BPB;
    trainer_kernel<<<blocks, NTHREADS>>>(outputs, tests, W1, b1, W2, b2, out, B);
}

// round 3
// speedup vs baseline: 1.0565x; 1.0565x over previous
#include <cuda_runtime.h>

#define WIRE_DIM   32
#define NUM_WIRES  64
#define ROW_ELEMS  (NUM_WIRES * WIRE_DIM)   // 2048 floats per batch row
#define BPB        4                        // batch rows per block (1 warp each)
#define NTHREADS   (BPB * 32)

typedef unsigned long long u64;

// ---- packed f32x2 helpers (Blackwell FFMA2 via PTX; ptxas will not auto-fuse) ----
__device__ __forceinline__ u64 pack2(float v) {
    u64 r;
    asm("mov.b64 %0, {%1, %1};" : "=l"(r) : "f"(v));
    return r;
}
__device__ __forceinline__ void ffma2(u64 &d, u64 a, u64 b) {
    asm("fma.rn.f32x2 %0, %1, %2, %0;" : "+l"(d) : "l"(a), "l"(b));
}
__device__ __forceinline__ float2 unpack2(u64 v) {
    float2 f;
    asm("mov.b64 {%0, %1}, %2;" : "=f"(f.x), "=f"(f.y) : "l"(v));
    return f;
}

__global__ __launch_bounds__(NTHREADS)
void trainer_kernel(const float* __restrict__ outputs,
                    const int* __restrict__ tests_i32,   // raw test buffer, width detected
                    const float* __restrict__ W1,
                    const float* __restrict__ b1,
                    const float* __restrict__ W2,
                    const float* __restrict__ b2,
                    float* __restrict__ out,
                    int B)
{
    // W1 padded to stride 12 (48B rows, 16B aligned -> LDS.128 weight fetches)
    __shared__ __align__(16) float sW1[64 * 12];            // 3072 B
    __shared__ __align__(16) float sb1[12];
    __shared__ __align__(16) float sW2[12];
    __shared__ __align__(16) float spc[BPB][12];            // person contribution
    // x rows: [wire][dim], chunk-rotated: float4 chunk c of wire w lives at
    // float offset w*32 + ((c+w)&7)*4  -> STS.128 and LDS.128 both conflict-free
    __shared__ __align__(16) float sx[BPB][NUM_WIRES * WIRE_DIM];  // 4*8KB

    const int tid  = threadIdx.x;
    const int warp = tid >> 5;
    const int lane = tid & 31;
    const int b    = blockIdx.x * BPB + warp;
    const bool valid = (b < B);

    // --- stage weights into padded smem (block-cooperative) ---
    #pragma unroll
    for (int i = tid; i < 640; i += NTHREADS) {
        int r = i / 10, h = i - r * 10;
        sW1[r * 12 + h] = W1[i];
    }
    if (tid < 10) { sb1[tid] = b1[tid]; sW2[tid] = W2[tid]; }

    // --- detect tests dtype: int64 pairs have zero high-words at odd int32 slots ---
    int hiword_or;
    {
        int v = tests_i32[2 * lane + 1];
        #pragma unroll
        for (int o = 16; o > 0; o >>= 1)
            v |= __shfl_xor_sync(0xffffffffu, v, o);
        hiword_or = v;
    }
    const bool is_i64 = (hiword_or == 0);

    // --- stage this warp's row: coalesced LDG.128 -> rotated STS.128 ---
    if (valid) {
        const float4* src = (const float4*)(outputs + (size_t)b * ROW_ELEMS);
        #pragma unroll
        for (int t = 0; t < 16; t++) {
            int    f = t * 32 + lane;          // float4 index 0..511
            float4 v = src[f];
            int    w = f >> 3;                 // wire
            int    c = f & 7;                  // chunk within wire
            int  off = w * 32 + (((c + w) & 7) << 2);
            *(float4*)&sx[warp][off] = v;      // phase-conflict-free STS.128
        }
    }
    __syncthreads();   // covers sW1/sb1/sW2 (block) and sx (warp)

    int person = 0, loc = 0;
    if (valid) {
        if (is_i64) { person = tests_i32[4 * b];  loc = tests_i32[4 * b + 2]; }
        else        { person = tests_i32[2 * b];  loc = tests_i32[2 * b + 1]; }
    }

    // --- person contribution pc[h] = b1[h] + sum_d pv[d]*W1[d][h]  (lanes 0..9) ---
    if (valid && lane < 10) {
        float pc = sb1[lane];
        const int pb = person * 32;
        #pragma unroll
        for (int c = 0; c < 8; c++) {
            float4 v = *(const float4*)&sx[warp][pb + (((c + person) & 7) << 2)]; // broadcast
            const int d = c * 4;
            pc += v.x * sW1[(d + 0) * 12 + lane];
            pc += v.y * sW1[(d + 1) * 12 + lane];
            pc += v.z * sW1[(d + 2) * 12 + lane];
            pc += v.w * sW1[(d + 3) * 12 + lane];
        }
        spc[warp][lane] = pc;
    }
    __syncwarp();

    if (valid) {
        // --- main MLP: lane handles wires l and l+32 (conflict-free LDS.128) ---
        u64 accA[5], accB[5];
        const u64* pcp = (const u64*)&spc[warp][0];
        #pragma unroll
        for (int h = 0; h < 5; h++) { accA[h] = pcp[h]; accB[h] = pcp[h]; }

        const int baseA = lane * 32;
        const int baseB = (lane + 32) * 32;

        #pragma unroll
        for (int c = 0; c < 8; c++) {
            const int rot = ((c + lane) & 7) << 2;       // same rotation for both wires
            float4 va = *(const float4*)&sx[warp][baseA + rot];
            float4 vb = *(const float4*)&sx[warp][baseB + rot];
            const float* wr = &sW1[(32 + c * 4) * 12];

            #pragma unroll
            for (int k = 0; k < 4; k++) {
                float xa_ = (k == 0) ? va.x : (k == 1) ? va.y : (k == 2) ? va.z : va.w;
                float xb_ = (k == 0) ? vb.x : (k == 1) ? vb.y : (k == 2) ? vb.z : vb.w;
                const float* wrow = wr + k * 12;
                u64 av = pack2(xa_);
                u64 bv = pack2(xb_);
                ulonglong2 w01 = *(const ulonglong2*)(wrow);       // LDS.128 (16B aligned)
                ulonglong2 w23 = *(const ulonglong2*)(wrow + 4);   // LDS.128
                u64        w4  = *(const u64*)(wrow + 8);          // LDS.64
                ffma2(accA[0], av, w01.x); ffma2(accB[0], bv, w01.x);
                ffma2(accA[1], av, w01.y); ffma2(accB[1], bv, w01.y);
                ffma2(accA[2], av, w23.x); ffma2(accB[2], bv, w23.x);
                ffma2(accA[3], av, w23.y); ffma2(accB[3], bv, w23.y);
                ffma2(accA[4], av, w4);    ffma2(accB[4], bv, w4);
            }
        }

        // --- relu + output layer -> two logits per lane (wires l, l+32) ---
        float b2v = __ldg(b2);
        float la = b2v, lb = b2v;
        #pragma unroll
        for (int h = 0; h < 5; h++) {
            float2 fa = unpack2(accA[h]);
            float2 fb = unpack2(accB[h]);
            float w0 = sW2[2 * h], w1 = sW2[2 * h + 1];
            la += fmaxf(fa.x, 0.f) * w0 + fmaxf(fa.y, 0.f) * w1;
            lb += fmaxf(fb.x, 0.f) * w0 + fmaxf(fb.y, 0.f) * w1;
        }

        // --- warp log-softmax over 64 logits, pick location ---
        float m = fmaxf(la, lb);
        #pragma unroll
        for (int o = 16; o > 0; o >>= 1)
            m = fmaxf(m, __shfl_xor_sync(0xffffffffu, m, o));
        float s = __expf(la - m) + __expf(lb - m);
        #pragma unroll
        for (int o = 16; o > 0; o >>= 1)
            s += __shfl_xor_sync(0xffffffffu, s, o);

        // wire w -> lane (w&31), slot (w>>5); loc is warp-uniform
        float cand = (loc >> 5) ? lb : la;
        cand = __shfl_sync(0xffffffffu, cand, loc & 31);

        if (lane == 0) out[b] = -(cand - m - __logf(s));
    }
}

extern "C" void kernel_launch(void* const* d_in, const int* in_sizes, int n_in,
                              void* d_out, int out_size)
{
    const float* outputs = (const float*)d_in[0];
    const int*   tests   = (const int*)d_in[1];
    const float* W1      = (const float*)d_in[2];
    const float* b1      = (const float*)d_in[3];
    const float* W2      = (const float*)d_in[4];
    const float* b2      = (const float*)d_in[5];
    float* out = (float*)d_out;
    int B = out_size;                 // one loss per batch element

    int blocks = (B + BPB - 1) / BPB;
    trainer_kernel<<<blocks, NTHREADS>>>(outputs, tests, W1, b1, W2, b2, out, B);
}

// round 4
// speedup vs baseline: 1.0935x; 1.0351x over previous
#include <cuda_runtime.h>

#define WIRE_DIM   32
#define NUM_WIRES  64
#define ROW_ELEMS  (NUM_WIRES * WIRE_DIM)   // 2048 floats per batch row
#define WPB        2                        // warps per block
#define RPW        2                        // rows per warp
#define NTHREADS   (WPB * 32)
#define RPB        (WPB * RPW)              // 4 rows per block

typedef unsigned long long u64;

// ---- packed f32x2 helpers (Blackwell FFMA2 via PTX) ----
__device__ __forceinline__ u64 pack2(float v) {
    u64 r; asm("mov.b64 %0, {%1, %1};" : "=l"(r) : "f"(v)); return r;
}
__device__ __forceinline__ void ffma2(u64 &d, u64 a, u64 b) {
    asm("fma.rn.f32x2 %0, %1, %2, %0;" : "+l"(d) : "l"(a), "l"(b));
}
__device__ __forceinline__ float2 unpack2(u64 v) {
    float2 f; asm("mov.b64 {%0, %1}, %2;" : "=f"(f.x), "=f"(f.y) : "l"(v)); return f;
}
__device__ __forceinline__ float selk(float4 v, int k) {
    return (k == 0) ? v.x : (k == 1) ? v.y : (k == 2) ? v.z : v.w;
}

__global__ __launch_bounds__(NTHREADS)
void trainer_kernel(const float* __restrict__ outputs,
                    const int* __restrict__ tests_i32,
                    const float* __restrict__ W1,
                    const float* __restrict__ b1,
                    const float* __restrict__ W2,
                    const float* __restrict__ b2,
                    float* __restrict__ out,
                    int B)
{
    __shared__ __align__(16) float sW1[64 * 12];               // stride-12 padded rows
    __shared__ __align__(16) float sb1[12];
    __shared__ __align__(16) float sW2[12];
    __shared__ __align__(16) float spc[WPB][RPW][12];
    __shared__ __align__(16) float sx[WPB][RPW][ROW_ELEMS];    // 32 KB

    const int tid  = threadIdx.x;
    const int warp = tid >> 5;
    const int lane = tid & 31;
    const int r0   = blockIdx.x * RPB + warp * RPW;            // rows r0, r0+1
    const bool v0  = (r0 < B), v1 = (r0 + 1 < B);

    // --- weights -> smem (block-cooperative) ---
    #pragma unroll
    for (int i = tid; i < 640; i += NTHREADS) {
        int r = i / 10, h = i - r * 10;
        sW1[r * 12 + h] = W1[i];
    }
    if (tid < 10) { sb1[tid] = b1[tid]; sW2[tid] = W2[tid]; }

    // --- detect tests dtype (int64 pairs have zero high-words at odd slots) ---
    int hv = tests_i32[2 * lane + 1];
    #pragma unroll
    for (int o = 16; o > 0; o >>= 1) hv |= __shfl_xor_sync(0xffffffffu, hv, o);
    const bool is_i64 = (hv == 0);

    // --- stage both rows: coalesced LDG.128 -> chunk-rotated STS.128 ---
    #pragma unroll
    for (int row = 0; row < RPW; row++) {
        int b = r0 + row;
        if (b < B) {
            const float4* src = (const float4*)(outputs + (size_t)b * ROW_ELEMS);
            #pragma unroll
            for (int t = 0; t < 16; t++) {
                int    f = t * 32 + lane;
                float4 v = src[f];
                int    w = f >> 3;
                int    c = f & 7;
                *(float4*)&sx[warp][row][w * 32 + (((c + w) & 7) << 2)] = v;
            }
        }
    }
    __syncthreads();

    // --- test indices for both rows (warp-uniform broadcast loads) ---
    int p0 = 0, l0 = 0, p1 = 0, l1 = 0;
    if (v0) {
        if (is_i64) { p0 = tests_i32[4 * r0];     l0 = tests_i32[4 * r0 + 2]; }
        else        { p0 = tests_i32[2 * r0];     l0 = tests_i32[2 * r0 + 1]; }
    }
    if (v1) {
        if (is_i64) { p1 = tests_i32[4 * r0 + 4]; l1 = tests_i32[4 * r0 + 6]; }
        else        { p1 = tests_i32[2 * r0 + 2]; l1 = tests_i32[2 * r0 + 3]; }
    }
    p0 &= 63; p1 &= 63;   // safety clamp

    // --- paired person pass: lanes 0-9 -> row0 h, lanes 16-25 -> row1 h ---
    {
        const int half = lane >> 4;
        const int hh   = lane & 15;
        const int pr   = half ? p1 : p0;
        if (hh < 10) {
            const float* px = &sx[warp][half][pr * 32];
            float pc = sb1[hh];
            #pragma unroll
            for (int c = 0; c < 8; c++) {
                float4 v = *(const float4*)&px[(((c + pr) & 7) << 2)];
                const int d = c * 4;
                pc += v.x * sW1[(d + 0) * 12 + hh];
                pc += v.y * sW1[(d + 1) * 12 + hh];
                pc += v.z * sW1[(d + 2) * 12 + hh];
                pc += v.w * sW1[(d + 3) * 12 + hh];
            }
            spc[warp][half][hh] = pc;
        }
        __syncwarp();
    }

    // --- merged main MLP for both rows: weights loaded once, used 4x ---
    u64 aA0[5], aB0[5], aA1[5], aB1[5];
    {
        const u64* pc0 = (const u64*)spc[warp][0];
        const u64* pc1 = (const u64*)spc[warp][1];
        #pragma unroll
        for (int h = 0; h < 5; h++) {
            aA0[h] = pc0[h]; aB0[h] = pc0[h];
            aA1[h] = pc1[h]; aB1[h] = pc1[h];
        }
    }

    const float* x0 = sx[warp][0];
    const float* x1 = sx[warp][1];
    const int bA = lane * 32;
    const int bB = (lane + 32) * 32;

    #pragma unroll
    for (int c = 0; c < 8; c++) {
        const int rot = ((c + lane) & 7) << 2;     // same for wires lane and lane+32
        float4 vA0 = *(const float4*)&x0[bA + rot];
        float4 vB0 = *(const float4*)&x0[bB + rot];
        float4 vA1 = *(const float4*)&x1[bA + rot];
        float4 vB1 = *(const float4*)&x1[bB + rot];
        const float* wr = &sW1[(32 + c * 4) * 12];

        #pragma unroll
        for (int k = 0; k < 4; k++) {
            const float* wrow = wr + k * 12;
            ulonglong2 w01 = *(const ulonglong2*)(wrow);      // LDS.128 broadcast
            ulonglong2 w23 = *(const ulonglong2*)(wrow + 4);  // LDS.128 broadcast
            u64        w4  = *(const u64*)(wrow + 8);         // LDS.64  broadcast
            u64 a0 = pack2(selk(vA0, k));
            u64 b0_ = pack2(selk(vB0, k));
            u64 a1 = pack2(selk(vA1, k));
            u64 b1_ = pack2(selk(vB1, k));
            ffma2(aA0[0], a0, w01.x); ffma2(aB0[0], b0_, w01.x);
            ffma2(aA1[0], a1, w01.x); ffma2(aB1[0], b1_, w01.x);
            ffma2(aA0[1], a0, w01.y); ffma2(aB0[1], b0_, w01.y);
            ffma2(aA1[1], a1, w01.y); ffma2(aB1[1], b1_, w01.y);
            ffma2(aA0[2], a0, w23.x); ffma2(aB0[2], b0_, w23.x);
            ffma2(aA1[2], a1, w23.x); ffma2(aB1[2], b1_, w23.x);
            ffma2(aA0[3], a0, w23.y); ffma2(aB0[3], b0_, w23.y);
            ffma2(aA1[3], a1, w23.y); ffma2(aB1[3], b1_, w23.y);
            ffma2(aA0[4], a0, w4);    ffma2(aB0[4], b0_, w4);
            ffma2(aA1[4], a1, w4);    ffma2(aB1[4], b1_, w4);
        }
    }

    // --- relu + output layer: two logits per lane per row ---
    const float b2v = __ldg(b2);
    float la0 = b2v, lb0 = b2v, la1 = b2v, lb1 = b2v;
    #pragma unroll
    for (int h = 0; h < 5; h++) {
        float w0 = sW2[2 * h], w1 = sW2[2 * h + 1];
        float2 f;
        f = unpack2(aA0[h]); la0 += fmaxf(f.x, 0.f) * w0 + fmaxf(f.y, 0.f) * w1;
        f = unpack2(aB0[h]); lb0 += fmaxf(f.x, 0.f) * w0 + fmaxf(f.y, 0.f) * w1;
        f = unpack2(aA1[h]); la1 += fmaxf(f.x, 0.f) * w0 + fmaxf(f.y, 0.f) * w1;
        f = unpack2(aB1[h]); lb1 += fmaxf(f.x, 0.f) * w0 + fmaxf(f.y, 0.f) * w1;
    }

    // --- two warp log-softmaxes (interleaved shuffles for ILP) ---
    float m0 = fmaxf(la0, lb0), m1 = fmaxf(la1, lb1);
    #pragma unroll
    for (int o = 16; o > 0; o >>= 1) {
        m0 = fmaxf(m0, __shfl_xor_sync(0xffffffffu, m0, o));
        m1 = fmaxf(m1, __shfl_xor_sync(0xffffffffu, m1, o));
    }
    float s0 = __expf(la0 - m0) + __expf(lb0 - m0);
    float s1 = __expf(la1 - m1) + __expf(lb1 - m1);
    #pragma unroll
    for (int o = 16; o > 0; o >>= 1) {
        s0 += __shfl_xor_sync(0xffffffffu, s0, o);
        s1 += __shfl_xor_sync(0xffffffffu, s1, o);
    }

    // wire w -> lane (w & 31), slot (w >> 5); loc warp-uniform
    float c0 = (l0 >> 5) ? lb0 : la0;
    float c1 = (l1 >> 5) ? lb1 : la1;
    c0 = __shfl_sync(0xffffffffu, c0, l0 & 31);
    c1 = __shfl_sync(0xffffffffu, c1, l1 & 31);

    if (lane == 0) {
        if (v0) out[r0]     = -(c0 - m0 - __logf(s0));
        if (v1) out[r0 + 1] = -(c1 - m1 - __logf(s1));
    }
}

extern "C" void kernel_launch(void* const* d_in, const int* in_sizes, int n_in,
                              void* d_out, int out_size)
{
    const float* outputs = (const float*)d_in[0];
    const int*   tests   = (const int*)d_in[1];
    const float* W1      = (const float*)d_in[2];
    const float* b1      = (const float*)d_in[3];
    const float* W2      = (const float*)d_in[4];
    const float* b2      = (const float*)d_in[5];
    float* out = (float*)d_out;
    int B = out_size;

    int blocks = (B + RPB - 1) / RPB;
    trainer_kernel<<<blocks, NTHREADS>>>(outputs, tests, W1, b1, W2, b2, out, B);
}